// round 15
// baseline (speedup 1.0000x reference)
#include <cuda_runtime.h>
#include <math.h>

#define BB 16
#define LL 200
#define HH 128
#define NHH 4
#define HSS 32
#define NBB 2
#define M_TOT (BB*LL)          // 3200
#define MH (M_TOT*HH)          // 409600
#define NEGVAL (-4294967295.0f)
#define LN_EPS 1e-8f
#define KROW 36                // padded shared row stride (floats), 16B-aligned
#define TROWS 257
#define FULLM 0xffffffffu
#define ATHREADS 1024
#define AWARPS (ATHREADS/32)
#define G_STRIDE 260
#define WT_OFF(type, layer) (((type)*2+(layer))*HH*HH)

// Scratch buffers + transposed weights + score matrices
__device__ float d_scratch[8 * MH];
__device__ float d_wt[10 * HH * HH];
__device__ float d_S1[BB * NHH * LL * LL];        // 10.24 MB
__device__ float d_G [BB * NHH * LL * G_STRIDE];  // 13.3 MB

// ---------------------------------------------------------------------------
// Transpose the 10 weight matrices [n][k] -> WT [k][n]
// ---------------------------------------------------------------------------
__global__ void transpose_w(const float* __restrict__ Wq, const float* __restrict__ Wk,
                            const float* __restrict__ Wv, const float* __restrict__ W1,
                            const float* __restrict__ W2, float* __restrict__ WT)
{
    __shared__ float t[32][33];
    int m = blockIdx.z;
    const float* src;
    switch (m >> 1) {
        case 0: src = Wq; break;
        case 1: src = Wk; break;
        case 2: src = Wv; break;
        case 3: src = W1; break;
        default: src = W2; break;
    }
    src += (m & 1) * HH * HH;
    float* dst = WT + m * HH * HH;

    int x  = blockIdx.x * 32 + threadIdx.x;
    int y0 = blockIdx.y * 32;
    for (int i = threadIdx.y; i < 32; i += 8)
        t[i][threadIdx.x] = src[(y0 + i) * HH + x];
    __syncthreads();
    int xo  = blockIdx.y * 32 + threadIdx.x;
    int yo0 = blockIdx.x * 32;
    for (int i = threadIdx.y; i < 32; i += 8)
        dst[(yo0 + i) * HH + xo] = t[threadIdx.x][i];
}

// ---------------------------------------------------------------------------
// GEMM core (256 threads, R12 shape): thread (cg, rg) -> rows rg*4..+3,
// cols float4 cg. As [32][128], Ws4 [128][128] float4 view.
// ---------------------------------------------------------------------------
__device__ __forceinline__ void gemm_core(const float* As, const float4* Ws4,
                                          int cg, int rg, float4 acc[4])
{
    #pragma unroll 8
    for (int k4 = 0; k4 < 32; k4++) {
        float4 w0 = Ws4[(4 * k4 + 0) * 32 + cg];
        float4 w1 = Ws4[(4 * k4 + 1) * 32 + cg];
        float4 w2 = Ws4[(4 * k4 + 2) * 32 + cg];
        float4 w3 = Ws4[(4 * k4 + 3) * 32 + cg];
        #pragma unroll
        for (int i = 0; i < 4; i++) {
            float4 a = ((const float4*)(As + (rg * 4 + i) * HH))[k4];
            acc[i].x += a.x * w0.x + a.y * w1.x + a.z * w2.x + a.w * w3.x;
            acc[i].y += a.x * w0.y + a.y * w1.y + a.z * w2.y + a.w * w3.y;
            acc[i].z += a.x * w0.z + a.y * w1.z + a.z * w2.z + a.w * w3.z;
            acc[i].w += a.x * w0.w + a.y * w1.w + a.z * w2.w + a.w * w3.w;
        }
    }
}

// LayerNorm a 32x128 tile in shared (in place); optionally also write to gout.
// 8 warps (256 threads).
__device__ __forceinline__ void ln_tile(float* As, const float* __restrict__ g,
                                        const float* __restrict__ bta,
                                        float* __restrict__ gout, int row0)
{
    int w = threadIdx.x >> 5, lane = threadIdx.x & 31;
    for (int r = w; r < 32; r += 8) {
        float* row = As + r * HH;
        float x0 = row[lane], x1 = row[lane + 32], x2 = row[lane + 64], x3 = row[lane + 96];
        float s = x0 + x1 + x2 + x3;
        #pragma unroll
        for (int o = 16; o; o >>= 1) s += __shfl_xor_sync(FULLM, s, o);
        float m = s * (1.0f / HH);
        float d0 = x0 - m, d1 = x1 - m, d2 = x2 - m, d3 = x3 - m;
        float v = d0 * d0 + d1 * d1 + d2 * d2 + d3 * d3;
        #pragma unroll
        for (int o = 16; o; o >>= 1) v += __shfl_xor_sync(FULLM, v, o);
        float rs = rsqrtf(v * (1.0f / HH) + LN_EPS);
        float y0 = d0 * rs * g[lane]      + bta[lane];
        float y1 = d1 * rs * g[lane + 32] + bta[lane + 32];
        float y2 = d2 * rs * g[lane + 64] + bta[lane + 64];
        float y3 = d3 * rs * g[lane + 96] + bta[lane + 96];
        row[lane] = y0; row[lane + 32] = y1; row[lane + 64] = y2; row[lane + 96] = y3;
        if (gout) {
            float* go = gout + (row0 + r) * HH;
            go[lane] = y0; go[lane + 32] = y1; go[lane + 64] = y2; go[lane + 96] = y3;
        }
    }
}

// ---------------------------------------------------------------------------
// QKV kernel (R12): grid (100, 3), 256 threads. z=0: Q = LN1(x)@WqT+bq (+Qin).
// z=1: K = x@WkT+bk+posK. z=2: V = x@WvT+bv+posV.
// x = seqs (layer>0) or the item embedding gathered on the fly (layer==0).
// ---------------------------------------------------------------------------
__global__ void __launch_bounds__(256)
qkv_kernel(const float* __restrict__ seqs, const float* __restrict__ WTbase, int layer,
           const int* __restrict__ log_seqs, const float* __restrict__ item_emb,
           const float* __restrict__ bq, const float* __restrict__ bk,
           const float* __restrict__ bv,
           const float* __restrict__ posK, const float* __restrict__ posV,
           const float* __restrict__ ln_g, const float* __restrict__ ln_b,
           float* __restrict__ Qin, float* __restrict__ Qb,
           float* __restrict__ Kb, float* __restrict__ Vb)
{
    extern __shared__ float sm[];
    float* As = sm;
    float4* Ws4 = (float4*)(sm + 32 * HH);
    int tid = threadIdx.x;
    int z = blockIdx.y;
    int row0 = blockIdx.x * 32;

    if (layer == 0) {
        const float sq = 11.313708498984760390f; // sqrt(128)
        #pragma unroll
        for (int idx = tid; idx < 32 * 32; idx += 256) {
            int r = idx >> 5, c4 = idx & 31;
            int item = log_seqs[row0 + r];
            float4 v = make_float4(0.f, 0.f, 0.f, 0.f);
            if (item != 0) {
                v = ((const float4*)(item_emb + item * HH))[c4];
                v.x *= sq; v.y *= sq; v.z *= sq; v.w *= sq;
            }
            ((float4*)As)[idx] = v;
        }
    } else {
        #pragma unroll
        for (int idx = tid; idx < 32 * 32; idx += 256)
            ((float4*)As)[idx] = ((const float4*)(seqs + row0 * HH))[idx];
    }
    const float4* Wsrc = (const float4*)(WTbase + WT_OFF(z, layer));
    #pragma unroll
    for (int idx = tid; idx < 4096; idx += 256)
        Ws4[idx] = Wsrc[idx];
    __syncthreads();
    if (z == 0) {
        ln_tile(As, ln_g, ln_b, Qin, row0);
        __syncthreads();
    }

    int cg = tid & 31, rg = tid >> 5;
    float4 acc[4];
    #pragma unroll
    for (int i = 0; i < 4; i++) acc[i] = make_float4(0.f, 0.f, 0.f, 0.f);
    gemm_core(As, Ws4, cg, rg, acc);

    const float* bias = (z == 0) ? bq : (z == 1) ? bk : bv;
    const float* posadd = (z == 1) ? posK : (z == 2) ? posV : nullptr;
    float* C = (z == 0) ? Qb : (z == 1) ? Kb : Vb;
    float4 bs = ((const float4*)bias)[cg];
    #pragma unroll
    for (int i = 0; i < 4; i++) {
        int m = row0 + rg * 4 + i;
        float4 v = acc[i];
        v.x += bs.x; v.y += bs.y; v.z += bs.z; v.w += bs.w;
        if (posadd) {
            float4 p = ((const float4*)(posadd + (m % LL) * HH))[cg];
            v.x += p.x; v.y += p.y; v.z += p.z; v.w += p.w;
        }
        ((float4*)(C + m * HH))[cg] = v;
    }
}

// ---------------------------------------------------------------------------
// S1/G kernel: per (b,h) computes S1[q][k] = Q[q]·K'[k] and
// G[q][t] = Q[q]·tmK[t]  (one fused GEMM, B = [K' ; tmK], 457 cols).
// grid (7, 8, 64): q-tile 32, n-tile 64. 256 threads; thread: 2 rows x 4 cols.
// ---------------------------------------------------------------------------
__global__ void __launch_bounds__(256)
s1g_kernel(const float* __restrict__ Qb, const float* __restrict__ Kb,
           const float* __restrict__ tmK,
           float* __restrict__ S1, float* __restrict__ G)
{
    __shared__ float Qs[32][33];
    __shared__ float Bs[64][33];
    int qt = blockIdx.x, nt = blockIdx.y, bh = blockIdx.z;
    int b = bh >> 2, h = bh & 3;
    int tid = threadIdx.x;
    int q0 = qt * 32, n0 = nt * 64;

    for (int i = tid; i < 32 * 32; i += 256) {
        int r = i >> 5, d = i & 31;
        int q = q0 + r; if (q > LL - 1) q = LL - 1;
        Qs[r][d] = Qb[(b * LL + q) * HH + h * HSS + d];
    }
    for (int i = tid; i < 64 * 32; i += 256) {
        int r = i >> 5, d = i & 31;
        int n = n0 + r;
        float v;
        if (n < LL) {
            v = Kb[(b * LL + n) * HH + h * HSS + d];
        } else {
            int t = n - LL; if (t > TROWS - 1) t = TROWS - 1;
            v = tmK[t * HH + h * HSS + d];
        }
        Bs[r][d] = v;
    }
    __syncthreads();

    int cg = tid & 15;      // cols 4cg..4cg+3
    int rg = tid >> 4;      // rows 2rg..2rg+1
    float acc[2][4] = {};
    #pragma unroll
    for (int k = 0; k < 32; k++) {
        float b0 = Bs[4 * cg + 0][k];
        float b1 = Bs[4 * cg + 1][k];
        float b2 = Bs[4 * cg + 2][k];
        float b3 = Bs[4 * cg + 3][k];
        #pragma unroll
        for (int i = 0; i < 2; i++) {
            float a = Qs[2 * rg + i][k];
            acc[i][0] += a * b0; acc[i][1] += a * b1;
            acc[i][2] += a * b2; acc[i][3] += a * b3;
        }
    }
    #pragma unroll
    for (int i = 0; i < 2; i++) {
        int q = q0 + 2 * rg + i;
        if (q >= LL) continue;
        #pragma unroll
        for (int j = 0; j < 4; j++) {
            int n = n0 + 4 * cg + j;
            if (n < LL)
                S1[(bh * LL + q) * LL + n] = acc[i][j];
            else if (n < LL + TROWS)
                G[(bh * LL + q) * G_STRIDE + (n - LL)] = acc[i][j];
        }
    }
}

// ---------------------------------------------------------------------------
// Fused FFN (R12): 256 threads; seqs2 = LN2(attn + Qin); hmid in smem;
// out = hmid@W2T + b2 + seqs2, pad-masked. smem 160KB.
// ---------------------------------------------------------------------------
__global__ void __launch_bounds__(256)
ffn_kernel(const float* __restrict__ attn, const float* __restrict__ Qin,
           const float* __restrict__ WTbase, int layer,
           const float* __restrict__ b1, const float* __restrict__ b2,
           const float* __restrict__ ln_g, const float* __restrict__ ln_b,
           const int* __restrict__ padidx, float* __restrict__ seqs_out)
{
    extern __shared__ float sm[];
    float*  As  = sm;                        // 32*128
    float4* W1s = (float4*)(sm + 32 * HH);   // 128*128
    float4* W2s = W1s + 4096;                // 128*128
    float*  Hs  = (float*)(W2s + 4096);      // 32*128

    int tid = threadIdx.x;
    int row0 = blockIdx.x * 32;

    #pragma unroll
    for (int idx = tid; idx < 32 * 32; idx += 256) {
        float4 a = ((const float4*)(attn + row0 * HH))[idx];
        float4 q = ((const float4*)(Qin  + row0 * HH))[idx];
        a.x += q.x; a.y += q.y; a.z += q.z; a.w += q.w;
        ((float4*)As)[idx] = a;
    }
    const float4* W1src = (const float4*)(WTbase + WT_OFF(3, layer));
    const float4* W2src = (const float4*)(WTbase + WT_OFF(4, layer));
    #pragma unroll
    for (int idx = tid; idx < 4096; idx += 256) {
        W1s[idx] = W1src[idx];
        W2s[idx] = W2src[idx];
    }
    __syncthreads();
    ln_tile(As, ln_g, ln_b, nullptr, row0);   // As := seqs2 tile
    __syncthreads();

    int cg = tid & 31, rg = tid >> 5;
    float4 acc[4];
    #pragma unroll
    for (int i = 0; i < 4; i++) acc[i] = make_float4(0.f, 0.f, 0.f, 0.f);
    gemm_core(As, W1s, cg, rg, acc);

    float4 b1s = ((const float4*)b1)[cg];
    #pragma unroll
    for (int i = 0; i < 4; i++) {
        float4 v = acc[i];
        v.x = fmaxf(v.x + b1s.x, 0.f); v.y = fmaxf(v.y + b1s.y, 0.f);
        v.z = fmaxf(v.z + b1s.z, 0.f); v.w = fmaxf(v.w + b1s.w, 0.f);
        ((float4*)(Hs + (rg * 4 + i) * HH))[cg] = v;
    }
    __syncthreads();

    #pragma unroll
    for (int i = 0; i < 4; i++) acc[i] = make_float4(0.f, 0.f, 0.f, 0.f);
    gemm_core(Hs, W2s, cg, rg, acc);

    float4 b2s = ((const float4*)b2)[cg];
    #pragma unroll
    for (int i = 0; i < 4; i++) {
        int m = row0 + rg * 4 + i;
        float4 v = acc[i];
        float4 r = ((const float4*)(As + (rg * 4 + i) * HH))[cg];   // seqs2 residual
        v.x += b2s.x + r.x; v.y += b2s.y + r.y;
        v.z += b2s.z + r.z; v.w += b2s.w + r.w;
        if (padidx[m] == 0) v = make_float4(0.f, 0.f, 0.f, 0.f);
        ((float4*)(seqs_out + m * HH))[cg] = v;
    }
}

// ---------------------------------------------------------------------------
// Attention v9: score from precomputed S1 + gathered G. grid (2, NHH, BB);
// 1024 threads (32 warps); warp-per-query. Stages only V' + tmV (65.8KB).
// Value: key-paired halves, lane owns dim pair (as R10).
// ---------------------------------------------------------------------------
__global__ void __launch_bounds__(ATHREADS)
attn_kernel(const float* __restrict__ S1,
            const float* __restrict__ G,
            const float* __restrict__ Vb,
            const int*  __restrict__ tmat,
            const float* __restrict__ tmVg,
            const int*  __restrict__ log_seqs,
            float* __restrict__ outp)
{
    extern __shared__ float sm[];
    float* Vsh  = sm;                       // 200*36
    float* tmVs = Vsh + LL * KROW;          // 257*36

    int qh = blockIdx.x;
    int h  = blockIdx.y;
    int b  = blockIdx.z;
    int bh = b * NHH + h;
    int tid = threadIdx.x;

    for (int idx = tid; idx < LL * 8; idx += ATHREADS) {
        int r = idx >> 3, d4 = idx & 7;
        ((float4*)(Vsh + r * KROW))[d4] =
            ((const float4*)(Vb + (b * LL + r) * HH + h * HSS))[d4];
    }
    for (int idx = tid; idx < TROWS * 8; idx += ATHREADS) {
        int r = idx >> 3, d4 = idx & 7;
        ((float4*)(tmVs + r * KROW))[d4] =
            ((const float4*)(tmVg + r * HH + h * HSS))[d4];
    }
    __syncthreads();

    const float scale = 0.17677669529663687f; // 1/sqrt(32)
    int w = tid >> 5, lane = tid & 31;
    int half = lane >> 4;                    // 0 or 1
    int dp   = lane & 15;                    // dim-pair index

    for (int q = qh + 2 * w; q < LL; q += 2 * AWARPS) {
        int rowq = b * LL + q;
        bool padq = (log_seqs[rowq] == 0);
        int kmax = padq ? LL : (q + 1);
        int nr = (kmax + 31) >> 5;           // <= 7

        float sr[7];
        int   tr[7];

        // preload tmat row (independent LDGs, MLP = nr)
        const int* trow = tmat + rowq * LL;
        #pragma unroll 7
        for (int j = 0; j < nr; j++) {
            int k = 32 * j + lane;
            tr[j] = trow[(k < kmax) ? k : (kmax - 1)];
        }

        // --- scores: sr = S1[q,k] + G[q, t] ---
        const float* S1row = S1 + (bh * LL + q) * LL;
        const float* Grow  = G  + (bh * LL + q) * G_STRIDE;
        #pragma unroll 7
        for (int j = 0; j < nr; j++) {
            int k = 32 * j + lane;
            bool val = (k < kmax);
            int kc = val ? k : (kmax - 1);
            float s1 = S1row[kc];
            float g  = Grow[tr[j]];
            sr[j] = (val && !padq) ? (s1 + g) * scale : NEGVAL;
        }

        // --- softmax (warp-local); invalid keys get p = 0 ---
        float m = -INFINITY;
        for (int j = 0; j < nr; j++) m = fmaxf(m, sr[j]);
        #pragma unroll
        for (int o = 16; o; o >>= 1) m = fmaxf(m, __shfl_xor_sync(FULLM, m, o));
        float sum = 0.f;
        for (int j = 0; j < nr; j++) {
            int k = 32 * j + lane;
            float e = (k < kmax) ? __expf(sr[j] - m) : 0.f;
            sr[j] = e;
            sum += e;
        }
        #pragma unroll
        for (int o = 16; o; o >>= 1) sum += __shfl_xor_sync(FULLM, sum, o);
        float inv = 1.0f / sum;

        // --- value accumulation: key-paired halves, lane owns dim pair ---
        float acc0 = 0.f, acc1 = 0.f;
        for (int j = 0; j < nr; j++) {
            int kbase = 32 * j;
            #pragma unroll 8
            for (int i = 0; i < 16; i++) {
                int kk = 2 * i + half;       // key slot within this row
                int k = kbase + kk;
                if (k >= kmax) k = kmax - 1; // clamp; p=0 for invalid slots
                float p = __shfl_sync(FULLM, sr[j], kk);
                int   t = __shfl_sync(FULLM, tr[j], kk);
                float2 v2 = *(const float2*)(Vsh + k * KROW + 2 * dp);
                float2 t2 = *(const float2*)(tmVs + t * KROW + 2 * dp);
                acc0 = fmaf(p, v2.x + t2.x, acc0);
                acc1 = fmaf(p, v2.y + t2.y, acc1);
            }
        }
        acc0 += __shfl_xor_sync(FULLM, acc0, 16);
        acc1 += __shfl_xor_sync(FULLM, acc1, 16);
        if (half == 0) {
            float2 o2 = make_float2(acc0 * inv, acc1 * inv);
            *(float2*)(outp + rowq * HH + h * HSS + 2 * dp) = o2;
        }
    }
}

// ---------------------------------------------------------------------------
// Final LN + logits fused. One block per row, 128 threads.
// ---------------------------------------------------------------------------
__global__ void logits_kernel(const float* __restrict__ seqs,
                              const float* __restrict__ lnf_g,
                              const float* __restrict__ lnf_b,
                              const float* __restrict__ item_emb,
                              const int* __restrict__ pos_seqs,
                              const int* __restrict__ neg_seqs,
                              float* __restrict__ out)
{
    int row = blockIdx.x;
    int t = threadIdx.x;
    float x = seqs[row * HH + t];

    __shared__ float red[8];
    float s = x;
    #pragma unroll
    for (int o = 16; o; o >>= 1) s += __shfl_xor_sync(FULLM, s, o);
    if ((t & 31) == 0) red[t >> 5] = s;
    __syncthreads();
    float m = (red[0] + red[1] + red[2] + red[3]) * (1.0f / HH);
    float d = x - m;
    float s2 = d * d;
    #pragma unroll
    for (int o = 16; o; o >>= 1) s2 += __shfl_xor_sync(FULLM, s2, o);
    __syncthreads();
    if ((t & 31) == 0) red[t >> 5] = s2;
    __syncthreads();
    float v = (red[0] + red[1] + red[2] + red[3]) * (1.0f / HH);
    float f = d * rsqrtf(v + LN_EPS) * lnf_g[t] + lnf_b[t];

    float p = f * item_emb[pos_seqs[row] * HH + t];
    float n = f * item_emb[neg_seqs[row] * HH + t];
    #pragma unroll
    for (int o = 16; o; o >>= 1) {
        p += __shfl_xor_sync(FULLM, p, o);
        n += __shfl_xor_sync(FULLM, n, o);
    }
    __syncthreads();
    if ((t & 31) == 0) { red[t >> 5] = p; red[4 + (t >> 5)] = n; }
    __syncthreads();
    if (t == 0) out[row]         = red[0] + red[1] + red[2] + red[3];
    if (t == 1) out[M_TOT + row] = red[4] + red[5] + red[6] + red[7];
}

// ---------------------------------------------------------------------------
extern "C" void kernel_launch(void* const* d_in, const int* in_sizes, int n_in,
                              void* d_out, int out_size)
{
    const int*   log_seqs = (const int*)  d_in[0];
    const int*   tmat     = (const int*)  d_in[1];
    const int*   pos_seqs = (const int*)  d_in[2];
    const int*   neg_seqs = (const int*)  d_in[3];
    const float* item_emb = (const float*)d_in[5];
    const float* pos_K    = (const float*)d_in[6];
    const float* pos_V    = (const float*)d_in[7];
    const float* tm_K     = (const float*)d_in[8];
    const float* tm_V     = (const float*)d_in[9];
    const float* Wq = (const float*)d_in[10]; const float* bq = (const float*)d_in[11];
    const float* Wk = (const float*)d_in[12]; const float* bk = (const float*)d_in[13];
    const float* Wv = (const float*)d_in[14]; const float* bv = (const float*)d_in[15];
    const float* ln1_g = (const float*)d_in[16]; const float* ln1_b = (const float*)d_in[17];
    const float* ln2_g = (const float*)d_in[18]; const float* ln2_b = (const float*)d_in[19];
    const float* W1 = (const float*)d_in[20]; const float* b1 = (const float*)d_in[21];
    const float* W2 = (const float*)d_in[22]; const float* b2 = (const float*)d_in[23];
    const float* lnf_g = (const float*)d_in[24]; const float* lnf_b = (const float*)d_in[25];
    float* out = (float*)d_out;

    float* S = nullptr;
    cudaGetSymbolAddress((void**)&S, d_scratch);
    float* WTbase = nullptr;
    cudaGetSymbolAddress((void**)&WTbase, d_wt);
    float* S1buf = nullptr;
    cudaGetSymbolAddress((void**)&S1buf, d_S1);
    float* Gbuf = nullptr;
    cudaGetSymbolAddress((void**)&Gbuf, d_G);

    float* seqs  = S + 0 * MH;
    float* Qin   = S + 1 * MH;
    float* Qb    = S + 2 * MH;
    float* Kb    = S + 3 * MH;
    float* Vb    = S + 4 * MH;
    float* attn  = S + 5 * MH;

    const int GEMM_SMEM = (32 * HH + HH * HH) * 4;                 // 80 KB
    const int FFN_SMEM  = (32 * HH + 2 * HH * HH + 32 * HH) * 4;   // 160 KB
    const int ATTN_SMEM = (LL * KROW + TROWS * KROW) * 4;          // ~65.8 KB
    cudaFuncSetAttribute(qkv_kernel, cudaFuncAttributeMaxDynamicSharedMemorySize, GEMM_SMEM);
    cudaFuncSetAttribute(ffn_kernel, cudaFuncAttributeMaxDynamicSharedMemorySize, FFN_SMEM);
    cudaFuncSetAttribute(attn_kernel, cudaFuncAttributeMaxDynamicSharedMemorySize, ATTN_SMEM);

    transpose_w<<<dim3(4, 4, 10), dim3(32, 8)>>>(Wq, Wk, Wv, W1, W2, WTbase);

    for (int i = 0; i < NBB; i++) {
        qkv_kernel<<<dim3(M_TOT / 32, 3), 256, GEMM_SMEM>>>(
            seqs, WTbase, i, log_seqs, item_emb,
            bq + i * HH, bk + i * HH, bv + i * HH,
            pos_K, pos_V, ln1_g + i * HH, ln1_b + i * HH, Qin, Qb, Kb, Vb);
        s1g_kernel<<<dim3(7, 8, BB * NHH), 256>>>(Qb, Kb, tm_K, S1buf, Gbuf);
        attn_kernel<<<dim3(2, NHH, BB), ATHREADS, ATTN_SMEM>>>(
            S1buf, Gbuf, Vb, tmat, tm_V, log_seqs, attn);
        ffn_kernel<<<M_TOT / 32, 256, FFN_SMEM>>>(
            attn, Qin, WTbase, i, b1 + i * HH, b2 + i * HH,
            ln2_g + i * HH, ln2_b + i * HH, log_seqs, seqs);
    }

    logits_kernel<<<M_TOT, 128>>>(seqs, lnf_g, lnf_b, item_emb,
                                  pos_seqs, neg_seqs, out);
}

// round 16
// speedup vs baseline: 1.0117x; 1.0117x over previous
#include <cuda_runtime.h>
#include <math.h>

#define BB 16
#define LL 200
#define HH 128
#define NHH 4
#define HSS 32
#define NBB 2
#define M_TOT (BB*LL)          // 3200
#define MH (M_TOT*HH)          // 409600
#define NEGVAL (-4294967295.0f)
#define LN_EPS 1e-8f
#define KROW 36                // padded shared row stride (floats), 16B-aligned
#define TROWS 257
#define FULLM 0xffffffffu
#define ATHREADS 1024
#define AWARPS (ATHREADS/32)
#define G_STRIDE 260
#define WT_OFF(type, layer) (((type)*2+(layer))*HH*HH)

// Scratch buffers + transposed weights + score matrices
__device__ float d_scratch[8 * MH];
__device__ float d_wt[10 * HH * HH];
__device__ float d_S1[BB * NHH * LL * LL];        // 10.24 MB
__device__ float d_G [BB * NHH * LL * G_STRIDE];  // 13.3 MB

// ---------------------------------------------------------------------------
// Transpose the 10 weight matrices [n][k] -> WT [k][n]
// ---------------------------------------------------------------------------
__global__ void transpose_w(const float* __restrict__ Wq, const float* __restrict__ Wk,
                            const float* __restrict__ Wv, const float* __restrict__ W1,
                            const float* __restrict__ W2, float* __restrict__ WT)
{
    __shared__ float t[32][33];
    int m = blockIdx.z;
    const float* src;
    switch (m >> 1) {
        case 0: src = Wq; break;
        case 1: src = Wk; break;
        case 2: src = Wv; break;
        case 3: src = W1; break;
        default: src = W2; break;
    }
    src += (m & 1) * HH * HH;
    float* dst = WT + m * HH * HH;

    int x  = blockIdx.x * 32 + threadIdx.x;
    int y0 = blockIdx.y * 32;
    for (int i = threadIdx.y; i < 32; i += 8)
        t[i][threadIdx.x] = src[(y0 + i) * HH + x];
    __syncthreads();
    int xo  = blockIdx.y * 32 + threadIdx.x;
    int yo0 = blockIdx.x * 32;
    for (int i = threadIdx.y; i < 32; i += 8)
        dst[(yo0 + i) * HH + xo] = t[threadIdx.x][i];
}

// ---------------------------------------------------------------------------
// GEMM core (256 threads): thread (cg, rg) -> rows rg*4..+3, cols float4 cg.
// ---------------------------------------------------------------------------
__device__ __forceinline__ void gemm_core(const float* As, const float4* Ws4,
                                          int cg, int rg, float4 acc[4])
{
    #pragma unroll 8
    for (int k4 = 0; k4 < 32; k4++) {
        float4 w0 = Ws4[(4 * k4 + 0) * 32 + cg];
        float4 w1 = Ws4[(4 * k4 + 1) * 32 + cg];
        float4 w2 = Ws4[(4 * k4 + 2) * 32 + cg];
        float4 w3 = Ws4[(4 * k4 + 3) * 32 + cg];
        #pragma unroll
        for (int i = 0; i < 4; i++) {
            float4 a = ((const float4*)(As + (rg * 4 + i) * HH))[k4];
            acc[i].x += a.x * w0.x + a.y * w1.x + a.z * w2.x + a.w * w3.x;
            acc[i].y += a.x * w0.y + a.y * w1.y + a.z * w2.y + a.w * w3.y;
            acc[i].z += a.x * w0.z + a.y * w1.z + a.z * w2.z + a.w * w3.z;
            acc[i].w += a.x * w0.w + a.y * w1.w + a.z * w2.w + a.w * w3.w;
        }
    }
}

// LayerNorm a 32x128 tile in shared (in place); 8 warps.
__device__ __forceinline__ void ln_tile(float* As, const float* __restrict__ g,
                                        const float* __restrict__ bta,
                                        float* __restrict__ gout, int row0)
{
    int w = threadIdx.x >> 5, lane = threadIdx.x & 31;
    for (int r = w; r < 32; r += 8) {
        float* row = As + r * HH;
        float x0 = row[lane], x1 = row[lane + 32], x2 = row[lane + 64], x3 = row[lane + 96];
        float s = x0 + x1 + x2 + x3;
        #pragma unroll
        for (int o = 16; o; o >>= 1) s += __shfl_xor_sync(FULLM, s, o);
        float m = s * (1.0f / HH);
        float d0 = x0 - m, d1 = x1 - m, d2 = x2 - m, d3 = x3 - m;
        float v = d0 * d0 + d1 * d1 + d2 * d2 + d3 * d3;
        #pragma unroll
        for (int o = 16; o; o >>= 1) v += __shfl_xor_sync(FULLM, v, o);
        float rs = rsqrtf(v * (1.0f / HH) + LN_EPS);
        float y0 = d0 * rs * g[lane]      + bta[lane];
        float y1 = d1 * rs * g[lane + 32] + bta[lane + 32];
        float y2 = d2 * rs * g[lane + 64] + bta[lane + 64];
        float y3 = d3 * rs * g[lane + 96] + bta[lane + 96];
        row[lane] = y0; row[lane + 32] = y1; row[lane + 64] = y2; row[lane + 96] = y3;
        if (gout) {
            float* go = gout + (row0 + r) * HH;
            go[lane] = y0; go[lane + 32] = y1; go[lane + 64] = y2; go[lane + 96] = y3;
        }
    }
}

// ---------------------------------------------------------------------------
// QKV kernel: grid (100, 3), 256 threads. z=0: Q = LN1(x)@WqT+bq (+Qin).
// z=1: K = x@WkT+bk+posK. z=2: V = x@WvT+bv+posV.
// ---------------------------------------------------------------------------
__global__ void __launch_bounds__(256)
qkv_kernel(const float* __restrict__ seqs, const float* __restrict__ WTbase, int layer,
           const int* __restrict__ log_seqs, const float* __restrict__ item_emb,
           const float* __restrict__ bq, const float* __restrict__ bk,
           const float* __restrict__ bv,
           const float* __restrict__ posK, const float* __restrict__ posV,
           const float* __restrict__ ln_g, const float* __restrict__ ln_b,
           float* __restrict__ Qin, float* __restrict__ Qb,
           float* __restrict__ Kb, float* __restrict__ Vb)
{
    extern __shared__ float sm[];
    float* As = sm;
    float4* Ws4 = (float4*)(sm + 32 * HH);
    int tid = threadIdx.x;
    int z = blockIdx.y;
    int row0 = blockIdx.x * 32;

    if (layer == 0) {
        const float sq = 11.313708498984760390f; // sqrt(128)
        #pragma unroll
        for (int idx = tid; idx < 32 * 32; idx += 256) {
            int r = idx >> 5, c4 = idx & 31;
            int item = log_seqs[row0 + r];
            float4 v = make_float4(0.f, 0.f, 0.f, 0.f);
            if (item != 0) {
                v = ((const float4*)(item_emb + item * HH))[c4];
                v.x *= sq; v.y *= sq; v.z *= sq; v.w *= sq;
            }
            ((float4*)As)[idx] = v;
        }
    } else {
        #pragma unroll
        for (int idx = tid; idx < 32 * 32; idx += 256)
            ((float4*)As)[idx] = ((const float4*)(seqs + row0 * HH))[idx];
    }
    const float4* Wsrc = (const float4*)(WTbase + WT_OFF(z, layer));
    #pragma unroll
    for (int idx = tid; idx < 4096; idx += 256)
        Ws4[idx] = Wsrc[idx];
    __syncthreads();
    if (z == 0) {
        ln_tile(As, ln_g, ln_b, Qin, row0);
        __syncthreads();
    }

    int cg = tid & 31, rg = tid >> 5;
    float4 acc[4];
    #pragma unroll
    for (int i = 0; i < 4; i++) acc[i] = make_float4(0.f, 0.f, 0.f, 0.f);
    gemm_core(As, Ws4, cg, rg, acc);

    const float* bias = (z == 0) ? bq : (z == 1) ? bk : bv;
    const float* posadd = (z == 1) ? posK : (z == 2) ? posV : nullptr;
    float* C = (z == 0) ? Qb : (z == 1) ? Kb : Vb;
    float4 bs = ((const float4*)bias)[cg];
    #pragma unroll
    for (int i = 0; i < 4; i++) {
        int m = row0 + rg * 4 + i;
        float4 v = acc[i];
        v.x += bs.x; v.y += bs.y; v.z += bs.z; v.w += bs.w;
        if (posadd) {
            float4 p = ((const float4*)(posadd + (m % LL) * HH))[cg];
            v.x += p.x; v.y += p.y; v.z += p.z; v.w += p.w;
        }
        ((float4*)(C + m * HH))[cg] = v;
    }
}

// ---------------------------------------------------------------------------
// S1/G kernel v2: per (b,h), S1[q][k] = Q[q]·K'[k], G[q][t] = Q[q]·tmK[t],
// fused B = [K' ; tmK] (457 cols, padded). Tiles: 64 q x 128 n.
// grid (4, 4, 64), 256 threads; thread computes 8 rows x 4 strided cols.
// Bs staged transposed [k][n] so b-loads are conflict-free; a-loads are
// warp-uniform broadcasts (rg = tid>>5 constant per warp).
// ---------------------------------------------------------------------------
__global__ void __launch_bounds__(256)
s1g_kernel(const float* __restrict__ Qb, const float* __restrict__ Kb,
           const float* __restrict__ tmK,
           float* __restrict__ S1, float* __restrict__ G)
{
    __shared__ float Qs[64][33];    // 8.4 KB
    __shared__ float Bs[32][132];   // 16.9 KB, transposed [k][n_local]
    int qt = blockIdx.x, nt = blockIdx.y, bh = blockIdx.z;
    int b = bh >> 2, h = bh & 3;
    int tid = threadIdx.x;
    int q0 = qt * 64, n0 = nt * 128;

    // stage Q tile (64 rows x 32 dims), q clamped
    for (int i = tid; i < 64 * 32; i += 256) {
        int r = i >> 5, d = i & 31;
        int q = q0 + r; if (q > LL - 1) q = LL - 1;
        Qs[r][d] = Qb[(b * LL + q) * HH + h * HSS + d];
    }
    // stage B tile transposed (128 n x 32 dims -> Bs[d][n])
    for (int i = tid; i < 128 * 32; i += 256) {
        int nl = i >> 5, d = i & 31;
        int n = n0 + nl;
        float v;
        if (n < LL) {
            v = Kb[(b * LL + n) * HH + h * HSS + d];
        } else {
            int t = n - LL; if (t > TROWS - 1) t = TROWS - 1;
            v = tmK[t * HH + h * HSS + d];
        }
        Bs[d][nl] = v;
    }
    __syncthreads();

    int cg = tid & 31;      // col lanes: n_local = cg + 32j
    int rg = tid >> 5;      // row group: rows rg*8 .. +7 (constant per warp)
    float acc[8][4];
    #pragma unroll
    for (int i = 0; i < 8; i++)
        #pragma unroll
        for (int j = 0; j < 4; j++) acc[i][j] = 0.f;

    #pragma unroll 4
    for (int k = 0; k < 32; k++) {
        float bv0 = Bs[k][cg];
        float bv1 = Bs[k][cg + 32];
        float bv2 = Bs[k][cg + 64];
        float bv3 = Bs[k][cg + 96];
        #pragma unroll
        for (int i = 0; i < 8; i++) {
            float a = Qs[rg * 8 + i][k];
            acc[i][0] = fmaf(a, bv0, acc[i][0]);
            acc[i][1] = fmaf(a, bv1, acc[i][1]);
            acc[i][2] = fmaf(a, bv2, acc[i][2]);
            acc[i][3] = fmaf(a, bv3, acc[i][3]);
        }
    }

    #pragma unroll
    for (int i = 0; i < 8; i++) {
        int q = q0 + rg * 8 + i;
        if (q >= LL) break;
        #pragma unroll
        for (int j = 0; j < 4; j++) {
            int n = n0 + cg + 32 * j;
            if (n < LL)
                S1[(bh * LL + q) * LL + n] = acc[i][j];
            else if (n - LL < TROWS)
                G[(bh * LL + q) * G_STRIDE + (n - LL)] = acc[i][j];
        }
    }
}

// ---------------------------------------------------------------------------
// Fused FFN: 256 threads; seqs2 = LN2(attn + Qin); hmid in smem;
// out = hmid@W2T + b2 + seqs2, pad-masked. smem 160KB.
// ---------------------------------------------------------------------------
__global__ void __launch_bounds__(256)
ffn_kernel(const float* __restrict__ attn, const float* __restrict__ Qin,
           const float* __restrict__ WTbase, int layer,
           const float* __restrict__ b1, const float* __restrict__ b2,
           const float* __restrict__ ln_g, const float* __restrict__ ln_b,
           const int* __restrict__ padidx, float* __restrict__ seqs_out)
{
    extern __shared__ float sm[];
    float*  As  = sm;                        // 32*128
    float4* W1s = (float4*)(sm + 32 * HH);   // 128*128
    float4* W2s = W1s + 4096;                // 128*128
    float*  Hs  = (float*)(W2s + 4096);      // 32*128

    int tid = threadIdx.x;
    int row0 = blockIdx.x * 32;

    #pragma unroll
    for (int idx = tid; idx < 32 * 32; idx += 256) {
        float4 a = ((const float4*)(attn + row0 * HH))[idx];
        float4 q = ((const float4*)(Qin  + row0 * HH))[idx];
        a.x += q.x; a.y += q.y; a.z += q.z; a.w += q.w;
        ((float4*)As)[idx] = a;
    }
    const float4* W1src = (const float4*)(WTbase + WT_OFF(3, layer));
    const float4* W2src = (const float4*)(WTbase + WT_OFF(4, layer));
    #pragma unroll
    for (int idx = tid; idx < 4096; idx += 256) {
        W1s[idx] = W1src[idx];
        W2s[idx] = W2src[idx];
    }
    __syncthreads();
    ln_tile(As, ln_g, ln_b, nullptr, row0);   // As := seqs2 tile
    __syncthreads();

    int cg = tid & 31, rg = tid >> 5;
    float4 acc[4];
    #pragma unroll
    for (int i = 0; i < 4; i++) acc[i] = make_float4(0.f, 0.f, 0.f, 0.f);
    gemm_core(As, W1s, cg, rg, acc);

    float4 b1s = ((const float4*)b1)[cg];
    #pragma unroll
    for (int i = 0; i < 4; i++) {
        float4 v = acc[i];
        v.x = fmaxf(v.x + b1s.x, 0.f); v.y = fmaxf(v.y + b1s.y, 0.f);
        v.z = fmaxf(v.z + b1s.z, 0.f); v.w = fmaxf(v.w + b1s.w, 0.f);
        ((float4*)(Hs + (rg * 4 + i) * HH))[cg] = v;
    }
    __syncthreads();

    #pragma unroll
    for (int i = 0; i < 4; i++) acc[i] = make_float4(0.f, 0.f, 0.f, 0.f);
    gemm_core(Hs, W2s, cg, rg, acc);

    float4 b2s = ((const float4*)b2)[cg];
    #pragma unroll
    for (int i = 0; i < 4; i++) {
        int m = row0 + rg * 4 + i;
        float4 v = acc[i];
        float4 r = ((const float4*)(As + (rg * 4 + i) * HH))[cg];   // seqs2 residual
        v.x += b2s.x + r.x; v.y += b2s.y + r.y;
        v.z += b2s.z + r.z; v.w += b2s.w + r.w;
        if (padidx[m] == 0) v = make_float4(0.f, 0.f, 0.f, 0.f);
        ((float4*)(seqs_out + m * HH))[cg] = v;
    }
}

// ---------------------------------------------------------------------------
// Attention v9: score from precomputed S1 + gathered G. grid (2, NHH, BB);
// 1024 threads; warp-per-query. Stages only V' + tmV (65.8KB).
// ---------------------------------------------------------------------------
__global__ void __launch_bounds__(ATHREADS)
attn_kernel(const float* __restrict__ S1,
            const float* __restrict__ G,
            const float* __restrict__ Vb,
            const int*  __restrict__ tmat,
            const float* __restrict__ tmVg,
            const int*  __restrict__ log_seqs,
            float* __restrict__ outp)
{
    extern __shared__ float sm[];
    float* Vsh  = sm;                       // 200*36
    float* tmVs = Vsh + LL * KROW;          // 257*36

    int qh = blockIdx.x;
    int h  = blockIdx.y;
    int b  = blockIdx.z;
    int bh = b * NHH + h;
    int tid = threadIdx.x;

    for (int idx = tid; idx < LL * 8; idx += ATHREADS) {
        int r = idx >> 3, d4 = idx & 7;
        ((float4*)(Vsh + r * KROW))[d4] =
            ((const float4*)(Vb + (b * LL + r) * HH + h * HSS))[d4];
    }
    for (int idx = tid; idx < TROWS * 8; idx += ATHREADS) {
        int r = idx >> 3, d4 = idx & 7;
        ((float4*)(tmVs + r * KROW))[d4] =
            ((const float4*)(tmVg + r * HH + h * HSS))[d4];
    }
    __syncthreads();

    const float scale = 0.17677669529663687f; // 1/sqrt(32)
    int w = tid >> 5, lane = tid & 31;
    int half = lane >> 4;                    // 0 or 1
    int dp   = lane & 15;                    // dim-pair index

    for (int q = qh + 2 * w; q < LL; q += 2 * AWARPS) {
        int rowq = b * LL + q;
        bool padq = (log_seqs[rowq] == 0);
        int kmax = padq ? LL : (q + 1);
        int nr = (kmax + 31) >> 5;           // <= 7

        float sr[7];
        int   tr[7];

        // preload tmat row (independent LDGs, MLP = nr)
        const int* trow = tmat + rowq * LL;
        #pragma unroll 7
        for (int j = 0; j < nr; j++) {
            int k = 32 * j + lane;
            tr[j] = trow[(k < kmax) ? k : (kmax - 1)];
        }

        // --- scores: sr = S1[q,k] + G[q, t] ---
        const float* S1row = S1 + (bh * LL + q) * LL;
        const float* Grow  = G  + (bh * LL + q) * G_STRIDE;
        #pragma unroll 7
        for (int j = 0; j < nr; j++) {
            int k = 32 * j + lane;
            bool val = (k < kmax);
            int kc = val ? k : (kmax - 1);
            float s1 = S1row[kc];
            float g  = Grow[tr[j]];
            sr[j] = (val && !padq) ? (s1 + g) * scale : NEGVAL;
        }

        // --- softmax (warp-local); invalid keys get p = 0 ---
        float m = -INFINITY;
        for (int j = 0; j < nr; j++) m = fmaxf(m, sr[j]);
        #pragma unroll
        for (int o = 16; o; o >>= 1) m = fmaxf(m, __shfl_xor_sync(FULLM, m, o));
        float sum = 0.f;
        for (int j = 0; j < nr; j++) {
            int k = 32 * j + lane;
            float e = (k < kmax) ? __expf(sr[j] - m) : 0.f;
            sr[j] = e;
            sum += e;
        }
        #pragma unroll
        for (int o = 16; o; o >>= 1) sum += __shfl_xor_sync(FULLM, sum, o);
        float inv = 1.0f / sum;

        // --- value accumulation: key-paired halves, lane owns dim pair ---
        float acc0 = 0.f, acc1 = 0.f;
        for (int j = 0; j < nr; j++) {
            int kbase = 32 * j;
            #pragma unroll 8
            for (int i = 0; i < 16; i++) {
                int kk = 2 * i + half;       // key slot within this row
                int k = kbase + kk;
                if (k >= kmax) k = kmax - 1; // clamp; p=0 for invalid slots
                float p = __shfl_sync(FULLM, sr[j], kk);
                int   t = __shfl_sync(FULLM, tr[j], kk);
                float2 v2 = *(const float2*)(Vsh + k * KROW + 2 * dp);
                float2 t2 = *(const float2*)(tmVs + t * KROW + 2 * dp);
                acc0 = fmaf(p, v2.x + t2.x, acc0);
                acc1 = fmaf(p, v2.y + t2.y, acc1);
            }
        }
        acc0 += __shfl_xor_sync(FULLM, acc0, 16);
        acc1 += __shfl_xor_sync(FULLM, acc1, 16);
        if (half == 0) {
            float2 o2 = make_float2(acc0 * inv, acc1 * inv);
            *(float2*)(outp + rowq * HH + h * HSS + 2 * dp) = o2;
        }
    }
}

// ---------------------------------------------------------------------------
// Final LN + logits fused. One block per row, 128 threads.
// ---------------------------------------------------------------------------
__global__ void logits_kernel(const float* __restrict__ seqs,
                              const float* __restrict__ lnf_g,
                              const float* __restrict__ lnf_b,
                              const float* __restrict__ item_emb,
                              const int* __restrict__ pos_seqs,
                              const int* __restrict__ neg_seqs,
                              float* __restrict__ out)
{
    int row = blockIdx.x;
    int t = threadIdx.x;
    float x = seqs[row * HH + t];

    __shared__ float red[8];
    float s = x;
    #pragma unroll
    for (int o = 16; o; o >>= 1) s += __shfl_xor_sync(FULLM, s, o);
    if ((t & 31) == 0) red[t >> 5] = s;
    __syncthreads();
    float m = (red[0] + red[1] + red[2] + red[3]) * (1.0f / HH);
    float d = x - m;
    float s2 = d * d;
    #pragma unroll
    for (int o = 16; o; o >>= 1) s2 += __shfl_xor_sync(FULLM, s2, o);
    __syncthreads();
    if ((t & 31) == 0) red[t >> 5] = s2;
    __syncthreads();
    float v = (red[0] + red[1] + red[2] + red[3]) * (1.0f / HH);
    float f = d * rsqrtf(v + LN_EPS) * lnf_g[t] + lnf_b[t];

    float p = f * item_emb[pos_seqs[row] * HH + t];
    float n = f * item_emb[neg_seqs[row] * HH + t];
    #pragma unroll
    for (int o = 16; o; o >>= 1) {
        p += __shfl_xor_sync(FULLM, p, o);
        n += __shfl_xor_sync(FULLM, n, o);
    }
    __syncthreads();
    if ((t & 31) == 0) { red[t >> 5] = p; red[4 + (t >> 5)] = n; }
    __syncthreads();
    if (t == 0) out[row]         = red[0] + red[1] + red[2] + red[3];
    if (t == 1) out[M_TOT + row] = red[4] + red[5] + red[6] + red[7];
}

// ---------------------------------------------------------------------------
extern "C" void kernel_launch(void* const* d_in, const int* in_sizes, int n_in,
                              void* d_out, int out_size)
{
    const int*   log_seqs = (const int*)  d_in[0];
    const int*   tmat     = (const int*)  d_in[1];
    const int*   pos_seqs = (const int*)  d_in[2];
    const int*   neg_seqs = (const int*)  d_in[3];
    const float* item_emb = (const float*)d_in[5];
    const float* pos_K    = (const float*)d_in[6];
    const float* pos_V    = (const float*)d_in[7];
    const float* tm_K     = (const float*)d_in[8];
    const float* tm_V     = (const float*)d_in[9];
    const float* Wq = (const float*)d_in[10]; const float* bq = (const float*)d_in[11];
    const float* Wk = (const float*)d_in[12]; const float* bk = (const float*)d_in[13];
    const float* Wv = (const float*)d_in[14]; const float* bv = (const float*)d_in[15];
    const float* ln1_g = (const float*)d_in[16]; const float* ln1_b = (const float*)d_in[17];
    const float* ln2_g = (const float*)d_in[18]; const float* ln2_b = (const float*)d_in[19];
    const float* W1 = (const float*)d_in[20]; const float* b1 = (const float*)d_in[21];
    const float* W2 = (const float*)d_in[22]; const float* b2 = (const float*)d_in[23];
    const float* lnf_g = (const float*)d_in[24]; const float* lnf_b = (const float*)d_in[25];
    float* out = (float*)d_out;

    float* S = nullptr;
    cudaGetSymbolAddress((void**)&S, d_scratch);
    float* WTbase = nullptr;
    cudaGetSymbolAddress((void**)&WTbase, d_wt);
    float* S1buf = nullptr;
    cudaGetSymbolAddress((void**)&S1buf, d_S1);
    float* Gbuf = nullptr;
    cudaGetSymbolAddress((void**)&Gbuf, d_G);

    float* seqs  = S + 0 * MH;
    float* Qin   = S + 1 * MH;
    float* Qb    = S + 2 * MH;
    float* Kb    = S + 3 * MH;
    float* Vb    = S + 4 * MH;
    float* attn  = S + 5 * MH;

    const int GEMM_SMEM = (32 * HH + HH * HH) * 4;                 // 80 KB
    const int FFN_SMEM  = (32 * HH + 2 * HH * HH + 32 * HH) * 4;   // 160 KB
    const int ATTN_SMEM = (LL * KROW + TROWS * KROW) * 4;          // ~65.8 KB
    cudaFuncSetAttribute(qkv_kernel, cudaFuncAttributeMaxDynamicSharedMemorySize, GEMM_SMEM);
    cudaFuncSetAttribute(ffn_kernel, cudaFuncAttributeMaxDynamicSharedMemorySize, FFN_SMEM);
    cudaFuncSetAttribute(attn_kernel, cudaFuncAttributeMaxDynamicSharedMemorySize, ATTN_SMEM);

    transpose_w<<<dim3(4, 4, 10), dim3(32, 8)>>>(Wq, Wk, Wv, W1, W2, WTbase);

    for (int i = 0; i < NBB; i++) {
        qkv_kernel<<<dim3(M_TOT / 32, 3), 256, GEMM_SMEM>>>(
            seqs, WTbase, i, log_seqs, item_emb,
            bq + i * HH, bk + i * HH, bv + i * HH,
            pos_K, pos_V, ln1_g + i * HH, ln1_b + i * HH, Qin, Qb, Kb, Vb);
        s1g_kernel<<<dim3(4, 4, BB * NHH), 256>>>(Qb, Kb, tm_K, S1buf, Gbuf);
        attn_kernel<<<dim3(2, NHH, BB), ATHREADS, ATTN_SMEM>>>(
            S1buf, Gbuf, Vb, tmat, tm_V, log_seqs, attn);
        ffn_kernel<<<M_TOT / 32, 256, FFN_SMEM>>>(
            attn, Qin, WTbase, i, b1 + i * HH, b2 + i * HH,
            ln2_g + i * HH, ln2_b + i * HH, log_seqs, seqs);
    }

    logits_kernel<<<M_TOT, 128>>>(seqs, lnf_g, lnf_b, item_emb,
                                  pos_seqs, neg_seqs, out);
}

// round 17
// speedup vs baseline: 1.2163x; 1.2023x over previous
#include <cuda_runtime.h>
#include <math.h>

#define BB 16
#define LL 200
#define HH 128
#define NHH 4
#define HSS 32
#define NBB 2
#define M_TOT (BB*LL)          // 3200
#define MH (M_TOT*HH)          // 409600
#define NEGVAL (-4294967295.0f)
#define LN_EPS 1e-8f
#define KROW 36                // padded shared row stride (floats), 16B-aligned
#define TROWS 257
#define FULLM 0xffffffffu
#define ATHREADS 768
#define AWARPS (ATHREADS/32)
#define WT_OFF(type, layer) (((type)*2+(layer))*HH*HH)

// Scratch buffers + transposed weights
__device__ float d_scratch[8 * MH];
__device__ float d_wt[10 * HH * HH];

// ---- packed f32x2 helpers (sm_100+) --------------------------------------
__device__ __forceinline__ unsigned long long f2_pack(float lo, float hi) {
    unsigned long long r;
    asm("mov.b64 %0, {%1, %2};" : "=l"(r) : "f"(lo), "f"(hi));
    return r;
}
__device__ __forceinline__ void f2_unpack(unsigned long long v, float& lo, float& hi) {
    asm("mov.b64 {%0, %1}, %2;" : "=f"(lo), "=f"(hi) : "l"(v));
}
__device__ __forceinline__ unsigned long long f2_add(unsigned long long a, unsigned long long b) {
    unsigned long long r;
    asm("add.rn.f32x2 %0, %1, %2;" : "=l"(r) : "l"(a), "l"(b));
    return r;
}
__device__ __forceinline__ unsigned long long f2_fma(unsigned long long a, unsigned long long b, unsigned long long c) {
    unsigned long long r;
    asm("fma.rn.f32x2 %0, %1, %2, %3;" : "=l"(r) : "l"(a), "l"(b), "l"(c));
    return r;
}

// ---------------------------------------------------------------------------
// Transpose the 10 weight matrices [n][k] -> WT [k][n]
// ---------------------------------------------------------------------------
__global__ void transpose_w(const float* __restrict__ Wq, const float* __restrict__ Wk,
                            const float* __restrict__ Wv, const float* __restrict__ W1,
                            const float* __restrict__ W2, float* __restrict__ WT)
{
    __shared__ float t[32][33];
    int m = blockIdx.z;
    const float* src;
    switch (m >> 1) {
        case 0: src = Wq; break;
        case 1: src = Wk; break;
        case 2: src = Wv; break;
        case 3: src = W1; break;
        default: src = W2; break;
    }
    src += (m & 1) * HH * HH;
    float* dst = WT + m * HH * HH;

    int x  = blockIdx.x * 32 + threadIdx.x;
    int y0 = blockIdx.y * 32;
    for (int i = threadIdx.y; i < 32; i += 8)
        t[i][threadIdx.x] = src[(y0 + i) * HH + x];
    __syncthreads();
    int xo  = blockIdx.y * 32 + threadIdx.x;
    int yo0 = blockIdx.x * 32;
    for (int i = threadIdx.y; i < 32; i += 8)
        dst[(yo0 + i) * HH + xo] = t[threadIdx.x][i];
}

// ---------------------------------------------------------------------------
// GEMM core (256 threads): thread (cg, rg) -> rows rg*4..+3, cols float4 cg.
// ---------------------------------------------------------------------------
__device__ __forceinline__ void gemm_core(const float* As, const float4* Ws4,
                                          int cg, int rg, float4 acc[4])
{
    #pragma unroll 8
    for (int k4 = 0; k4 < 32; k4++) {
        float4 w0 = Ws4[(4 * k4 + 0) * 32 + cg];
        float4 w1 = Ws4[(4 * k4 + 1) * 32 + cg];
        float4 w2 = Ws4[(4 * k4 + 2) * 32 + cg];
        float4 w3 = Ws4[(4 * k4 + 3) * 32 + cg];
        #pragma unroll
        for (int i = 0; i < 4; i++) {
            float4 a = ((const float4*)(As + (rg * 4 + i) * HH))[k4];
            acc[i].x += a.x * w0.x + a.y * w1.x + a.z * w2.x + a.w * w3.x;
            acc[i].y += a.x * w0.y + a.y * w1.y + a.z * w2.y + a.w * w3.y;
            acc[i].z += a.x * w0.z + a.y * w1.z + a.z * w2.z + a.w * w3.z;
            acc[i].w += a.x * w0.w + a.y * w1.w + a.z * w2.w + a.w * w3.w;
        }
    }
}

// LayerNorm a 32x128 tile in shared (in place); 8 warps.
__device__ __forceinline__ void ln_tile(float* As, const float* __restrict__ g,
                                        const float* __restrict__ bta,
                                        float* __restrict__ gout, int row0)
{
    int w = threadIdx.x >> 5, lane = threadIdx.x & 31;
    for (int r = w; r < 32; r += 8) {
        float* row = As + r * HH;
        float x0 = row[lane], x1 = row[lane + 32], x2 = row[lane + 64], x3 = row[lane + 96];
        float s = x0 + x1 + x2 + x3;
        #pragma unroll
        for (int o = 16; o; o >>= 1) s += __shfl_xor_sync(FULLM, s, o);
        float m = s * (1.0f / HH);
        float d0 = x0 - m, d1 = x1 - m, d2 = x2 - m, d3 = x3 - m;
        float v = d0 * d0 + d1 * d1 + d2 * d2 + d3 * d3;
        #pragma unroll
        for (int o = 16; o; o >>= 1) v += __shfl_xor_sync(FULLM, v, o);
        float rs = rsqrtf(v * (1.0f / HH) + LN_EPS);
        float y0 = d0 * rs * g[lane]      + bta[lane];
        float y1 = d1 * rs * g[lane + 32] + bta[lane + 32];
        float y2 = d2 * rs * g[lane + 64] + bta[lane + 64];
        float y3 = d3 * rs * g[lane + 96] + bta[lane + 96];
        row[lane] = y0; row[lane + 32] = y1; row[lane + 64] = y2; row[lane + 96] = y3;
        if (gout) {
            float* go = gout + (row0 + r) * HH;
            go[lane] = y0; go[lane + 32] = y1; go[lane + 64] = y2; go[lane + 96] = y3;
        }
    }
}

// ---------------------------------------------------------------------------
// QKV kernel: grid (100, 3), 256 threads. z=0: Q = LN1(x)@WqT+bq (+Qin).
// z=1: K = x@WkT+bk+posK. z=2: V = x@WvT+bv+posV.
// x = seqs (layer>0) or the item embedding gathered on the fly (layer==0).
// ---------------------------------------------------------------------------
__global__ void __launch_bounds__(256)
qkv_kernel(const float* __restrict__ seqs, const float* __restrict__ WTbase, int layer,
           const int* __restrict__ log_seqs, const float* __restrict__ item_emb,
           const float* __restrict__ bq, const float* __restrict__ bk,
           const float* __restrict__ bv,
           const float* __restrict__ posK, const float* __restrict__ posV,
           const float* __restrict__ ln_g, const float* __restrict__ ln_b,
           float* __restrict__ Qin, float* __restrict__ Qb,
           float* __restrict__ Kb, float* __restrict__ Vb)
{
    extern __shared__ float sm[];
    float* As = sm;
    float4* Ws4 = (float4*)(sm + 32 * HH);
    int tid = threadIdx.x;
    int z = blockIdx.y;
    int row0 = blockIdx.x * 32;

    if (layer == 0) {
        const float sq = 11.313708498984760390f; // sqrt(128)
        #pragma unroll
        for (int idx = tid; idx < 32 * 32; idx += 256) {
            int r = idx >> 5, c4 = idx & 31;
            int item = log_seqs[row0 + r];
            float4 v = make_float4(0.f, 0.f, 0.f, 0.f);
            if (item != 0) {
                v = ((const float4*)(item_emb + item * HH))[c4];
                v.x *= sq; v.y *= sq; v.z *= sq; v.w *= sq;
            }
            ((float4*)As)[idx] = v;
        }
    } else {
        #pragma unroll
        for (int idx = tid; idx < 32 * 32; idx += 256)
            ((float4*)As)[idx] = ((const float4*)(seqs + row0 * HH))[idx];
    }
    const float4* Wsrc = (const float4*)(WTbase + WT_OFF(z, layer));
    #pragma unroll
    for (int idx = tid; idx < 4096; idx += 256)
        Ws4[idx] = Wsrc[idx];
    __syncthreads();
    if (z == 0) {
        ln_tile(As, ln_g, ln_b, Qin, row0);
        __syncthreads();
    }

    int cg = tid & 31, rg = tid >> 5;
    float4 acc[4];
    #pragma unroll
    for (int i = 0; i < 4; i++) acc[i] = make_float4(0.f, 0.f, 0.f, 0.f);
    gemm_core(As, Ws4, cg, rg, acc);

    const float* bias = (z == 0) ? bq : (z == 1) ? bk : bv;
    const float* posadd = (z == 1) ? posK : (z == 2) ? posV : nullptr;
    float* C = (z == 0) ? Qb : (z == 1) ? Kb : Vb;
    float4 bs = ((const float4*)bias)[cg];
    #pragma unroll
    for (int i = 0; i < 4; i++) {
        int m = row0 + rg * 4 + i;
        float4 v = acc[i];
        v.x += bs.x; v.y += bs.y; v.z += bs.z; v.w += bs.w;
        if (posadd) {
            float4 p = ((const float4*)(posadd + (m % LL) * HH))[cg];
            v.x += p.x; v.y += p.y; v.z += p.z; v.w += p.w;
        }
        ((float4*)(C + m * HH))[cg] = v;
    }
}

// ---------------------------------------------------------------------------
// Fused FFN: 256 threads; seqs2 = LN2(attn + Qin); hmid in smem;
// out = hmid@W2T + b2 + seqs2, pad-masked. smem 160KB.
// ---------------------------------------------------------------------------
__global__ void __launch_bounds__(256)
ffn_kernel(const float* __restrict__ attn, const float* __restrict__ Qin,
           const float* __restrict__ WTbase, int layer,
           const float* __restrict__ b1, const float* __restrict__ b2,
           const float* __restrict__ ln_g, const float* __restrict__ ln_b,
           const int* __restrict__ padidx, float* __restrict__ seqs_out)
{
    extern __shared__ float sm[];
    float*  As  = sm;                        // 32*128
    float4* W1s = (float4*)(sm + 32 * HH);   // 128*128
    float4* W2s = W1s + 4096;                // 128*128
    float*  Hs  = (float*)(W2s + 4096);      // 32*128

    int tid = threadIdx.x;
    int row0 = blockIdx.x * 32;

    #pragma unroll
    for (int idx = tid; idx < 32 * 32; idx += 256) {
        float4 a = ((const float4*)(attn + row0 * HH))[idx];
        float4 q = ((const float4*)(Qin  + row0 * HH))[idx];
        a.x += q.x; a.y += q.y; a.z += q.z; a.w += q.w;
        ((float4*)As)[idx] = a;
    }
    const float4* W1src = (const float4*)(WTbase + WT_OFF(3, layer));
    const float4* W2src = (const float4*)(WTbase + WT_OFF(4, layer));
    #pragma unroll
    for (int idx = tid; idx < 4096; idx += 256) {
        W1s[idx] = W1src[idx];
        W2s[idx] = W2src[idx];
    }
    __syncthreads();
    ln_tile(As, ln_g, ln_b, nullptr, row0);   // As := seqs2 tile
    __syncthreads();

    int cg = tid & 31, rg = tid >> 5;
    float4 acc[4];
    #pragma unroll
    for (int i = 0; i < 4; i++) acc[i] = make_float4(0.f, 0.f, 0.f, 0.f);
    gemm_core(As, W1s, cg, rg, acc);

    float4 b1s = ((const float4*)b1)[cg];
    #pragma unroll
    for (int i = 0; i < 4; i++) {
        float4 v = acc[i];
        v.x = fmaxf(v.x + b1s.x, 0.f); v.y = fmaxf(v.y + b1s.y, 0.f);
        v.z = fmaxf(v.z + b1s.z, 0.f); v.w = fmaxf(v.w + b1s.w, 0.f);
        ((float4*)(Hs + (rg * 4 + i) * HH))[cg] = v;
    }
    __syncthreads();

    #pragma unroll
    for (int i = 0; i < 4; i++) acc[i] = make_float4(0.f, 0.f, 0.f, 0.f);
    gemm_core(Hs, W2s, cg, rg, acc);

    float4 b2s = ((const float4*)b2)[cg];
    #pragma unroll
    for (int i = 0; i < 4; i++) {
        int m = row0 + rg * 4 + i;
        float4 v = acc[i];
        float4 r = ((const float4*)(As + (rg * 4 + i) * HH))[cg];   // seqs2 residual
        v.x += b2s.x + r.x; v.y += b2s.y + r.y;
        v.z += b2s.z + r.z; v.w += b2s.w + r.w;
        if (padidx[m] == 0) v = make_float4(0.f, 0.f, 0.f, 0.f);
        ((float4*)(seqs_out + m * HH))[cg] = v;
    }
}

// ---------------------------------------------------------------------------
// Attention (R12 best + clamp removal): grid (2, NHH, BB); 768 threads;
// warp-per-query. Score: lane-per-key packed f32x2 dot; Value: key-paired
// halves, lane owns a dim pair. Out-of-range smem reads are deliberately
// allowed (they stay inside this block's smem allocation) and neutralized
// via the NEGVAL predicate (score) or p=0 (value). tmat keeps its clamp
// (global memory bounds).
// ---------------------------------------------------------------------------
__global__ void __launch_bounds__(ATHREADS)
attn_kernel(const float* __restrict__ Qb,
            const float* __restrict__ Kb,
            const float* __restrict__ Vb,
            const int*  __restrict__ tmat,
            const float* __restrict__ tmKg,
            const float* __restrict__ tmVg,
            const int*  __restrict__ log_seqs,
            float* __restrict__ outp)
{
    extern __shared__ float sm[];
    float* Ksh  = sm;                       // 200*36
    float* Vsh  = Ksh + LL * KROW;          // 200*36
    float* tmKs = Vsh + LL * KROW;          // 257*36
    float* tmVs = tmKs + TROWS * KROW;      // 257*36

    int qh = blockIdx.x;
    int h  = blockIdx.y;
    int b  = blockIdx.z;
    int tid = threadIdx.x;

    for (int idx = tid; idx < LL * 8; idx += ATHREADS) {
        int r = idx >> 3, d4 = idx & 7;
        ((float4*)(Ksh + r * KROW))[d4] =
            ((const float4*)(Kb + (b * LL + r) * HH + h * HSS))[d4];
        ((float4*)(Vsh + r * KROW))[d4] =
            ((const float4*)(Vb + (b * LL + r) * HH + h * HSS))[d4];
    }
    for (int idx = tid; idx < TROWS * 8; idx += ATHREADS) {
        int r = idx >> 3, d4 = idx & 7;
        ((float4*)(tmKs + r * KROW))[d4] =
            ((const float4*)(tmKg + r * HH + h * HSS))[d4];
        ((float4*)(tmVs + r * KROW))[d4] =
            ((const float4*)(tmVg + r * HH + h * HSS))[d4];
    }
    __syncthreads();

    const float scale = 0.17677669529663687f; // 1/sqrt(32)
    int w = tid >> 5, lane = tid & 31;
    int half = lane >> 4;                    // 0 or 1
    int dp   = lane & 15;                    // dim-pair index (dims 2dp, 2dp+1)

    for (int q = qh + 2 * w; q < LL; q += 2 * AWARPS) {
        int rowq = b * LL + q;
        bool padq = (log_seqs[rowq] == 0);
        int kmax = padq ? LL : (q + 1);
        int nr = (kmax + 31) >> 5;           // <= 7

        // Q packed straight from global
        unsigned long long qp2[16];
        {
            const ulonglong2* qrow = (const ulonglong2*)(Qb + rowq * HH + h * HSS);
            #pragma unroll
            for (int j = 0; j < 8; j++) {
                ulonglong2 v = qrow[j];
                qp2[2 * j]     = v.x;
                qp2[2 * j + 1] = v.y;
            }
        }

        float sr[7];
        int   tr[7];

        // preload tmat row (independent LDGs; clamp needed: global bounds)
        const int* trow = tmat + rowq * LL;
        #pragma unroll 7
        for (int j = 0; j < nr; j++) {
            int k = 32 * j + lane;
            tr[j] = trow[(k < kmax) ? k : (kmax - 1)];
        }

        // --- scores: lane owns key k = 32j + lane (no smem clamp) ---
        for (int j = 0; j < nr; j++) {
            int k = 32 * j + lane;
            bool val = (k < kmax);
            const ulonglong2* kp = (const ulonglong2*)(Ksh + k * KROW);
            const ulonglong2* tp = (const ulonglong2*)(tmKs + tr[j] * KROW);
            unsigned long long acc2 = f2_pack(0.f, 0.f);
            #pragma unroll
            for (int d4 = 0; d4 < 8; d4++) {
                ulonglong2 kf = kp[d4];
                ulonglong2 tf = tp[d4];
                acc2 = f2_fma(qp2[2 * d4 + 0], f2_add(kf.x, tf.x), acc2);
                acc2 = f2_fma(qp2[2 * d4 + 1], f2_add(kf.y, tf.y), acc2);
            }
            float a0, a1;
            f2_unpack(acc2, a0, a1);
            sr[j] = (val && !padq) ? (a0 + a1) * scale : NEGVAL;
        }

        // --- softmax (warp-local); invalid keys get p = 0 ---
        float m = -INFINITY;
        for (int j = 0; j < nr; j++) m = fmaxf(m, sr[j]);
        #pragma unroll
        for (int o = 16; o; o >>= 1) m = fmaxf(m, __shfl_xor_sync(FULLM, m, o));
        float sum = 0.f;
        for (int j = 0; j < nr; j++) {
            int k = 32 * j + lane;
            float e = (k < kmax) ? __expf(sr[j] - m) : 0.f;
            sr[j] = e;
            sum += e;
        }
        #pragma unroll
        for (int o = 16; o; o >>= 1) sum += __shfl_xor_sync(FULLM, sum, o);
        float inv = 1.0f / sum;

        // --- value accumulation: key-paired halves (no smem clamp: p=0) ---
        unsigned long long acc2 = f2_pack(0.f, 0.f);
        for (int j = 0; j < nr; j++) {
            int kbase = 32 * j;
            #pragma unroll 8
            for (int i = 0; i < 16; i++) {
                int kk = 2 * i + half;       // key slot within this row
                int k = kbase + kk;          // may exceed kmax; p=0 then
                float p = __shfl_sync(FULLM, sr[j], kk);
                int   t = __shfl_sync(FULLM, tr[j], kk);
                unsigned long long v2 =
                    *(const unsigned long long*)(Vsh + k * KROW + 2 * dp);
                unsigned long long t2 =
                    *(const unsigned long long*)(tmVs + t * KROW + 2 * dp);
                acc2 = f2_fma(f2_pack(p, p), f2_add(v2, t2), acc2);
            }
        }
        float a0, a1;
        f2_unpack(acc2, a0, a1);
        a0 += __shfl_xor_sync(FULLM, a0, 16);
        a1 += __shfl_xor_sync(FULLM, a1, 16);
        if (half == 0) {
            float2 o2 = make_float2(a0 * inv, a1 * inv);
            *(float2*)(outp + rowq * HH + h * HSS + 2 * dp) = o2;
        }
    }
}

// ---------------------------------------------------------------------------
// Final LN + logits fused. One block per row, 128 threads.
// ---------------------------------------------------------------------------
__global__ void logits_kernel(const float* __restrict__ seqs,
                              const float* __restrict__ lnf_g,
                              const float* __restrict__ lnf_b,
                              const float* __restrict__ item_emb,
                              const int* __restrict__ pos_seqs,
                              const int* __restrict__ neg_seqs,
                              float* __restrict__ out)
{
    int row = blockIdx.x;
    int t = threadIdx.x;
    float x = seqs[row * HH + t];

    __shared__ float red[8];
    float s = x;
    #pragma unroll
    for (int o = 16; o; o >>= 1) s += __shfl_xor_sync(FULLM, s, o);
    if ((t & 31) == 0) red[t >> 5] = s;
    __syncthreads();
    float m = (red[0] + red[1] + red[2] + red[3]) * (1.0f / HH);
    float d = x - m;
    float s2 = d * d;
    #pragma unroll
    for (int o = 16; o; o >>= 1) s2 += __shfl_xor_sync(FULLM, s2, o);
    __syncthreads();
    if ((t & 31) == 0) red[t >> 5] = s2;
    __syncthreads();
    float v = (red[0] + red[1] + red[2] + red[3]) * (1.0f / HH);
    float f = d * rsqrtf(v + LN_EPS) * lnf_g[t] + lnf_b[t];

    float p = f * item_emb[pos_seqs[row] * HH + t];
    float n = f * item_emb[neg_seqs[row] * HH + t];
    #pragma unroll
    for (int o = 16; o; o >>= 1) {
        p += __shfl_xor_sync(FULLM, p, o);
        n += __shfl_xor_sync(FULLM, n, o);
    }
    __syncthreads();
    if ((t & 31) == 0) { red[t >> 5] = p; red[4 + (t >> 5)] = n; }
    __syncthreads();
    if (t == 0) out[row]         = red[0] + red[1] + red[2] + red[3];
    if (t == 1) out[M_TOT + row] = red[4] + red[5] + red[6] + red[7];
}

// ---------------------------------------------------------------------------
extern "C" void kernel_launch(void* const* d_in, const int* in_sizes, int n_in,
                              void* d_out, int out_size)
{
    const int*   log_seqs = (const int*)  d_in[0];
    const int*   tmat     = (const int*)  d_in[1];
    const int*   pos_seqs = (const int*)  d_in[2];
    const int*   neg_seqs = (const int*)  d_in[3];
    const float* item_emb = (const float*)d_in[5];
    const float* pos_K    = (const float*)d_in[6];
    const float* pos_V    = (const float*)d_in[7];
    const float* tm_K     = (const float*)d_in[8];
    const float* tm_V     = (const float*)d_in[9];
    const float* Wq = (const float*)d_in[10]; const float* bq = (const float*)d_in[11];
    const float* Wk = (const float*)d_in[12]; const float* bk = (const float*)d_in[13];
    const float* Wv = (const float*)d_in[14]; const float* bv = (const float*)d_in[15];
    const float* ln1_g = (const float*)d_in[16]; const float* ln1_b = (const float*)d_in[17];
    const float* ln2_g = (const float*)d_in[18]; const float* ln2_b = (const float*)d_in[19];
    const float* W1 = (const float*)d_in[20]; const float* b1 = (const float*)d_in[21];
    const float* W2 = (const float*)d_in[22]; const float* b2 = (const float*)d_in[23];
    const float* lnf_g = (const float*)d_in[24]; const float* lnf_b = (const float*)d_in[25];
    float* out = (float*)d_out;

    float* S = nullptr;
    cudaGetSymbolAddress((void**)&S, d_scratch);
    float* WTbase = nullptr;
    cudaGetSymbolAddress((void**)&WTbase, d_wt);

    float* seqs  = S + 0 * MH;
    float* Qin   = S + 1 * MH;
    float* Qb    = S + 2 * MH;
    float* Kb    = S + 3 * MH;
    float* Vb    = S + 4 * MH;
    float* attn  = S + 5 * MH;

    const int GEMM_SMEM = (32 * HH + HH * HH) * 4;                 // 80 KB
    const int FFN_SMEM  = (32 * HH + 2 * HH * HH + 32 * HH) * 4;   // 160 KB
    const int ATTN_SMEM = (2 * LL * KROW + 2 * TROWS * KROW) * 4;  // ~131.6 KB
    cudaFuncSetAttribute(qkv_kernel, cudaFuncAttributeMaxDynamicSharedMemorySize, GEMM_SMEM);
    cudaFuncSetAttribute(ffn_kernel, cudaFuncAttributeMaxDynamicSharedMemorySize, FFN_SMEM);
    cudaFuncSetAttribute(attn_kernel, cudaFuncAttributeMaxDynamicSharedMemorySize, ATTN_SMEM);

    transpose_w<<<dim3(4, 4, 10), dim3(32, 8)>>>(Wq, Wk, Wv, W1, W2, WTbase);

    for (int i = 0; i < NBB; i++) {
        qkv_kernel<<<dim3(M_TOT / 32, 3), 256, GEMM_SMEM>>>(
            seqs, WTbase, i, log_seqs, item_emb,
            bq + i * HH, bk + i * HH, bv + i * HH,
            pos_K, pos_V, ln1_g + i * HH, ln1_b + i * HH, Qin, Qb, Kb, Vb);
        attn_kernel<<<dim3(2, NHH, BB), ATHREADS, ATTN_SMEM>>>(
            Qb, Kb, Vb, tmat, tm_K, tm_V, log_seqs, attn);
        ffn_kernel<<<M_TOT / 32, 256, FFN_SMEM>>>(
            attn, Qin, WTbase, i, b1 + i * HH, b2 + i * HH,
            ln2_g + i * HH, ln2_b + i * HH, log_seqs, seqs);
    }

    logits_kernel<<<M_TOT, 128>>>(seqs, lnf_g, lnf_b, item_emb,
                                  pos_seqs, neg_seqs, out);
}